// round 8
// baseline (speedup 1.0000x reference)
#include <cuda_runtime.h>
#include <cuda_bf16.h>
#include <math_constants.h>
#include <cstdint>

#define N_NODES 50000
#define HID     128
#define E_EDGES 640000
#define ATT_SLOPE 0.2f
#define OUT_SLOPE 0.01f

// ---------------- scratch (device globals; no allocation allowed) ----------
__device__ float g_xl[N_NODES * HID];
__device__ float g_xr[N_NODES * HID];
__device__ float g_h1[N_NODES * HID];
__device__ int   g_deg[N_NODES];
__device__ int   g_rowptr[N_NODES + 1];
__device__ int   g_cursor[N_NODES];
__device__ int   g_esrc[E_EDGES];
// bf16 hi/lo images: X rows [row][64 u32], W [n=256][64 u32]
__device__ uint32_t g_xhi[N_NODES * 64];
__device__ uint32_t g_xlo[N_NODES * 64];
__device__ uint32_t g_w1hi[256 * 64];
__device__ uint32_t g_w1lo[256 * 64];
__device__ uint32_t g_w2hi[256 * 64];
__device__ uint32_t g_w2lo[256 * 64];

__device__ __forceinline__ float lrelu(float x, float s) { return x > 0.f ? x : s * x; }

__device__ __forceinline__ uint32_t s2u(const void* p) {
    uint32_t a;
    asm("{ .reg .u64 t; cvta.to.shared.u64 t, %1; cvt.u32.u64 %0, t; }" : "=r"(a) : "l"(p));
    return a;
}
__device__ __forceinline__ void cpasync16(uint32_t dst, const void* src) {
    asm volatile("cp.async.cg.shared.global [%0], [%1], 16;" :: "r"(dst), "l"(src));
}
__device__ __forceinline__ void cpasync16p(uint32_t dst, const void* src, int sz) {
    asm volatile("cp.async.cg.shared.global [%0], [%1], 16, %2;"
                 :: "r"(dst), "l"(src), "r"(sz));
}

// ---------------- CSR build (unchanged) -------------------------------------
__global__ void k_zero_deg() {
    int i = blockIdx.x * blockDim.x + threadIdx.x;
    if (i < N_NODES) g_deg[i] = 0;
}
__global__ void k_hist(const int* __restrict__ dst) {
    int i = blockIdx.x * blockDim.x + threadIdx.x;
    if (i < E_EDGES) atomicAdd(&g_deg[dst[i]], 1);
}
__global__ void __launch_bounds__(1024) k_scan() {
    __shared__ int ssum[1024];
    const int t = threadIdx.x;
    const int CH = (N_NODES + 1023) / 1024;
    const int base = t * CH;
    int s = 0;
    for (int j = 0; j < CH; j++) { int idx = base + j; if (idx < N_NODES) s += g_deg[idx]; }
    ssum[t] = s;
    __syncthreads();
    for (int off = 1; off < 1024; off <<= 1) {
        int v = (t >= off) ? ssum[t - off] : 0;
        __syncthreads();
        ssum[t] += v;
        __syncthreads();
    }
    int run = (t == 0) ? 0 : ssum[t - 1];
    for (int j = 0; j < CH; j++) {
        int idx = base + j;
        if (idx < N_NODES) { g_rowptr[idx] = run; g_cursor[idx] = run; run += g_deg[idx]; }
    }
    if (t == 1023) g_rowptr[N_NODES] = ssum[1023];
}
__global__ void k_scatter(const int* __restrict__ src, const int* __restrict__ dst) {
    int i = blockIdx.x * blockDim.x + threadIdx.x;
    if (i < E_EDGES) {
        int p = atomicAdd(&g_cursor[dst[i]], 1);
        g_esrc[p] = src[i];
    }
}

// ---------------- bf16 split helpers ----------------------------------------
__device__ __forceinline__ uint32_t pack_hi(float x, float y) {
    __nv_bfloat16 hx = __float2bfloat16(x), hy = __float2bfloat16(y);
    return ((uint32_t)__bfloat16_as_ushort(hy) << 16) | __bfloat16_as_ushort(hx);
}
__device__ __forceinline__ uint32_t pack_lo(float x, float y) {
    __nv_bfloat16 hx = __float2bfloat16(x), hy = __float2bfloat16(y);
    __nv_bfloat16 lx = __float2bfloat16(x - __bfloat162float(hx));
    __nv_bfloat16 ly = __float2bfloat16(y - __bfloat162float(hy));
    return ((uint32_t)__bfloat16_as_ushort(ly) << 16) | __bfloat16_as_ushort(lx);
}

__global__ void k_prepw(const float* __restrict__ wl, const float* __restrict__ wr,
                        uint32_t* __restrict__ hi, uint32_t* __restrict__ lo) {
    int i = blockIdx.x * blockDim.x + threadIdx.x;
    if (i >= 256 * 64) return;
    int n = i >> 6, p = i & 63;
    const float* wp = ((n < 128) ? wl : wr) + (size_t)(n & 127) * 128 + p * 2;
    float2 v = *(const float2*)wp;
    hi[i] = pack_hi(v.x, v.y);
    lo[i] = pack_lo(v.x, v.y);
}

__global__ void k_prepx(const float* __restrict__ X) {
    int i = blockIdx.x * blockDim.x + threadIdx.x;
    if (i >= N_NODES * 64) return;
    float2 v = *(const float2*)(X + (size_t)i * 2);
    g_xhi[i] = pack_hi(v.x, v.y);
    g_xlo[i] = pack_lo(v.x, v.y);
}

// ---------------- split-bf16 HMMA GEMM (unchanged from R7) ------------------
#define LDP   136
#define LDPU  68
#define SMEM_AHI 0
#define SMEM_ALO (SMEM_AHI + 128 * LDP * 2)
#define SMEM_BHI (SMEM_ALO + 128 * LDP * 2)
#define SMEM_BLO (SMEM_BHI + 64 * LDP * 2)
#define SMEM_TOT (SMEM_BLO + 64 * LDP * 2)

__device__ __forceinline__ void ldsm4(uint32_t& r0, uint32_t& r1, uint32_t& r2,
                                      uint32_t& r3, uint32_t addr) {
    asm volatile("ldmatrix.sync.aligned.m8n8.x4.shared.b16 {%0,%1,%2,%3}, [%4];"
                 : "=r"(r0), "=r"(r1), "=r"(r2), "=r"(r3) : "r"(addr));
}
__device__ __forceinline__ void mma16816(float* c, const uint32_t* a, const uint32_t* b) {
    asm volatile(
        "mma.sync.aligned.m16n8k16.row.col.f32.bf16.bf16.f32 "
        "{%0,%1,%2,%3}, {%4,%5,%6,%7}, {%8,%9}, {%0,%1,%2,%3};"
        : "+f"(c[0]), "+f"(c[1]), "+f"(c[2]), "+f"(c[3])
        : "r"(a[0]), "r"(a[1]), "r"(a[2]), "r"(a[3]), "r"(b[0]), "r"(b[1]));
}

__global__ void __launch_bounds__(256, 2)
k_gemm_tc(const uint32_t* __restrict__ whi, const uint32_t* __restrict__ wlo) {
    extern __shared__ char smem[];
    const uint32_t sb = s2u(smem);
    const int tid  = threadIdx.x;
    const int warp = tid >> 5;
    const int lane = tid & 31;
    const int mblk = blockIdx.x >> 2;
    const int nblk = blockIdx.x & 3;

    for (int c = tid; c < 2048; c += 256) {
        int row = c >> 4, seg = c & 15;
        long grow = (long)mblk * 128 + row;
        int sz = (grow < N_NODES) ? 16 : 0;
        uint32_t doff = (uint32_t)(row * (LDP * 2) + seg * 16);
        size_t soff = (size_t)grow * 256 + seg * 16;
        cpasync16p(sb + SMEM_AHI + doff, (const char*)g_xhi + soff, sz);
        cpasync16p(sb + SMEM_ALO + doff, (const char*)g_xlo + soff, sz);
    }
    {
        const char* bh = (const char*)(whi + (size_t)nblk * 64 * 64);
        const char* bl = (const char*)(wlo + (size_t)nblk * 64 * 64);
        for (int c = tid; c < 1024; c += 256) {
            int row = c >> 4, seg = c & 15;
            uint32_t doff = (uint32_t)(row * (LDP * 2) + seg * 16);
            uint32_t soff = (uint32_t)(row * 256 + seg * 16);
            cpasync16(sb + SMEM_BHI + doff, bh + soff);
            cpasync16(sb + SMEM_BLO + doff, bl + soff);
        }
    }
    asm volatile("cp.async.commit_group;" ::: "memory");
    asm volatile("cp.async.wait_group 0;" ::: "memory");
    __syncthreads();

    const int wm = (warp >> 1) * 32;
    const int wn = (warp & 1) * 32;
    float c[2][4][4];
#pragma unroll
    for (int mi = 0; mi < 2; mi++)
#pragma unroll
        for (int ni = 0; ni < 4; ni++)
#pragma unroll
            for (int q = 0; q < 4; q++) c[mi][ni][q] = 0.f;

    const uint32_t aRowOff = (uint32_t)((wm + (lane & 15)) * LDP + ((lane >> 4) << 3)) << 1;
    const uint32_t bRowOff = (uint32_t)((wn + ((lane >> 4) << 3) + (lane & 7)) * LDP
                                        + (((lane >> 3) & 1) << 3)) << 1;

#pragma unroll
    for (int term = 0; term < 3; term++) {
        const uint32_t Ab = sb + (term == 2 ? SMEM_ALO : SMEM_AHI) + aRowOff;
        const uint32_t Bb = sb + (term == 1 ? SMEM_BLO : SMEM_BHI) + bRowOff;
#pragma unroll
        for (int k0 = 0; k0 < 128; k0 += 16) {
            uint32_t a[2][4];
            ldsm4(a[0][0], a[0][1], a[0][2], a[0][3], Ab + (k0 << 1));
            ldsm4(a[1][0], a[1][1], a[1][2], a[1][3], Ab + ((16 * LDP) << 1) + (k0 << 1));
            uint32_t b[4][2];
#pragma unroll
            for (int nq = 0; nq < 2; nq++) {
                uint32_t r0, r1, r2, r3;
                ldsm4(r0, r1, r2, r3, Bb + ((nq * 16 * LDP) << 1) + (k0 << 1));
                b[nq * 2][0] = r0; b[nq * 2][1] = r1;
                b[nq * 2 + 1][0] = r2; b[nq * 2 + 1][1] = r3;
            }
#pragma unroll
            for (int mi = 0; mi < 2; mi++)
#pragma unroll
                for (int ni = 0; ni < 4; ni++)
                    mma16816(c[mi][ni], a[mi], b[ni]);
        }
    }

    float* buf = (nblk < 2) ? g_xl : g_xr;
    const int colbase = ((nblk * 64) & 127) + wn + (lane & 3) * 2;
#pragma unroll
    for (int mi = 0; mi < 2; mi++) {
#pragma unroll
        for (int half = 0; half < 2; half++) {
            long row = (long)mblk * 128 + wm + mi * 16 + (lane >> 2) + half * 8;
            if (row >= N_NODES) continue;
            float* rp = buf + row * HID + colbase;
#pragma unroll
            for (int ni = 0; ni < 4; ni++) {
                float2 v = make_float2(c[mi][ni][half * 2], c[mi][ni][half * 2 + 1]);
                *(float2*)(rp + ni * 8) = v;
            }
        }
    }
}

// ---------------- fused per-node attention v2 -------------------------------
// One warp per node; two 16-lane groups process 2 edges concurrently.
// Lane gl (=lane&15) owns channels [8gl, 8gl+8). Head reduce = 3 xor-shfls
// within 8-lane subgroups. Cross-group combine at the end (xor 16).
template <int LAYER>
__global__ void k_node(const float* __restrict__ att, const float* __restrict__ b,
                       float* __restrict__ outbuf) {
    const int n    = (blockIdx.x * blockDim.x + threadIdx.x) >> 5;
    const int lane = threadIdx.x & 31;
    if (n >= N_NODES) return;
    const int grp = lane >> 4;
    const int gl  = lane & 15;

    const int beg = g_rowptr[n];
    const int end = g_rowptr[n + 1];

    const float4* xrp = (const float4*)(g_xr + (size_t)n * HID + gl * 8);
    const float4 xr0 = __ldg(xrp);
    const float4 xr1 = __ldg(xrp + 1);
    const float4* atp = (const float4*)(att + gl * 8);
    const float4 at0 = __ldg(atp);
    const float4 at1 = __ldg(atp + 1);

    float acc[8] = {0.f, 0.f, 0.f, 0.f, 0.f, 0.f, 0.f, 0.f};
    float sum = 0.f;

    for (int i0 = beg; i0 < end; i0 += 32) {
        const int cnt = min(32, end - i0);
        const int sid = g_esrc[min(i0 + lane, end - 1)];

        // prologue: fetch for t=0
        int s = __shfl_sync(0xffffffffu, sid, min(grp, cnt - 1));
        const float4* xp = (const float4*)(g_xl + (size_t)s * HID + gl * 8);
        float4 a0 = __ldg(xp), a1 = __ldg(xp + 1);

        for (int t = 0; t < cnt; t += 2) {
            // prefetch pair t+2 (uniform condition; hides L2 latency)
            float4 n0, n1;
            const bool havenext = (t + 2 < cnt);
            const int sn = __shfl_sync(0xffffffffu, sid, min(t + 2 + grp, cnt - 1));
            if (havenext) {
                const float4* np = (const float4*)(g_xl + (size_t)sn * HID + gl * 8);
                n0 = __ldg(np); n1 = __ldg(np + 1);
            }
            // attention logit: partial over this lane's 8 channels
            float p = lrelu(a0.x + xr0.x, ATT_SLOPE) * at0.x
                    + lrelu(a0.y + xr0.y, ATT_SLOPE) * at0.y
                    + lrelu(a0.z + xr0.z, ATT_SLOPE) * at0.z
                    + lrelu(a0.w + xr0.w, ATT_SLOPE) * at0.w
                    + lrelu(a1.x + xr1.x, ATT_SLOPE) * at1.x
                    + lrelu(a1.y + xr1.y, ATT_SLOPE) * at1.y
                    + lrelu(a1.z + xr1.z, ATT_SLOPE) * at1.z
                    + lrelu(a1.w + xr1.w, ATT_SLOPE) * at1.w;
            // reduce within 8-lane head subgroup
            p += __shfl_xor_sync(0xffffffffu, p, 4);
            p += __shfl_xor_sync(0xffffffffu, p, 2);
            p += __shfl_xor_sync(0xffffffffu, p, 1);
            const float e = (t + grp < cnt) ? __expf(p) : 0.f;
            sum += e;
            acc[0] = fmaf(e, a0.x, acc[0]);
            acc[1] = fmaf(e, a0.y, acc[1]);
            acc[2] = fmaf(e, a0.z, acc[2]);
            acc[3] = fmaf(e, a0.w, acc[3]);
            acc[4] = fmaf(e, a1.x, acc[4]);
            acc[5] = fmaf(e, a1.y, acc[5]);
            acc[6] = fmaf(e, a1.z, acc[6]);
            acc[7] = fmaf(e, a1.w, acc[7]);
            a0 = n0; a1 = n1;
        }
    }

    // cross-group combine (lane <-> lane^16 share channels AND head)
#pragma unroll
    for (int q = 0; q < 8; q++)
        acc[q] += __shfl_xor_sync(0xffffffffu, acc[q], 16);
    sum += __shfl_xor_sync(0xffffffffu, sum, 16);

    if (grp == 0) {
        const float inv = 1.f / (sum + 1e-16f);
        const float4* bp = (const float4*)(b + gl * 8);
        const float4 b0 = __ldg(bp), b1 = __ldg(bp + 1);
        float o[8];
        o[0] = fmaf(acc[0], inv, b0.x); o[1] = fmaf(acc[1], inv, b0.y);
        o[2] = fmaf(acc[2], inv, b0.z); o[3] = fmaf(acc[3], inv, b0.w);
        o[4] = fmaf(acc[4], inv, b1.x); o[5] = fmaf(acc[5], inv, b1.y);
        o[6] = fmaf(acc[6], inv, b1.z); o[7] = fmaf(acc[7], inv, b1.w);

        float* dstp = outbuf + (size_t)n * HID + gl * 8;
        if (LAYER == 1) {
#pragma unroll
            for (int q = 0; q < 8; q++) o[q] = lrelu(o[q], OUT_SLOPE);
            *(float4*)dstp       = make_float4(o[0], o[1], o[2], o[3]);
            *(float4*)(dstp + 4) = make_float4(o[4], o[5], o[6], o[7]);
            // bf16 hi/lo image of h1 for the layer-2 GEMM
            const size_t ib = (size_t)n * 64 + gl * 4;
            uint4 hi = make_uint4(pack_hi(o[0], o[1]), pack_hi(o[2], o[3]),
                                  pack_hi(o[4], o[5]), pack_hi(o[6], o[7]));
            uint4 lo = make_uint4(pack_lo(o[0], o[1]), pack_lo(o[2], o[3]),
                                  pack_lo(o[4], o[5]), pack_lo(o[6], o[7]));
            *(uint4*)(g_xhi + ib) = hi;
            *(uint4*)(g_xlo + ib) = lo;
        } else {
            const float4* hp = (const float4*)(g_h1 + (size_t)n * HID + gl * 8);
            const float4 h0 = __ldg(hp), h1v = __ldg(hp + 1);
            *(float4*)dstp       = make_float4(o[0] + h0.x, o[1] + h0.y,
                                               o[2] + h0.z, o[3] + h0.w);
            *(float4*)(dstp + 4) = make_float4(o[4] + h1v.x, o[5] + h1v.y,
                                               o[6] + h1v.z, o[7] + h1v.w);
        }
    }
}

// ---------------- launch ----------------
extern "C" void kernel_launch(void* const* d_in, const int* in_sizes, int n_in,
                              void* d_out, int out_size) {
    const float* x    = (const float*)d_in[0];
    const int*   ei   = (const int*)d_in[1];
    const float* wl1  = (const float*)d_in[2];
    const float* wr1  = (const float*)d_in[3];
    const float* att1 = (const float*)d_in[4];
    const float* b1   = (const float*)d_in[5];
    const float* wl2  = (const float*)d_in[6];
    const float* wr2  = (const float*)d_in[7];
    const float* att2 = (const float*)d_in[8];
    const float* b2   = (const float*)d_in[9];
    float* out = (float*)d_out;

    const int* src = ei;
    const int* dst = ei + E_EDGES;

    void* h1_ptr = nullptr;
    cudaGetSymbolAddress(&h1_ptr, g_h1);
    void *w1hi, *w1lo, *w2hi, *w2lo;
    cudaGetSymbolAddress(&w1hi, g_w1hi);
    cudaGetSymbolAddress(&w1lo, g_w1lo);
    cudaGetSymbolAddress(&w2hi, g_w2hi);
    cudaGetSymbolAddress(&w2lo, g_w2lo);

    static cudaStream_t s1 = nullptr;
    static cudaEvent_t ev_fork = nullptr, ev_join = nullptr;
    if (s1 == nullptr) {
        cudaStreamCreateWithFlags(&s1, cudaStreamNonBlocking);
        cudaEventCreateWithFlags(&ev_fork, cudaEventDisableTiming);
        cudaEventCreateWithFlags(&ev_join, cudaEventDisableTiming);
    }

    cudaFuncSetAttribute(k_gemm_tc, cudaFuncAttributeMaxDynamicSharedMemorySize, SMEM_TOT);

    const int gemm_blocks = ((N_NODES + 127) / 128) * 4;    // 1564
    const int node_blocks = (N_NODES * 32 + 255) / 256;     // 6250
    const int e_blocks    = (E_EDGES + 255) / 256;
    const int n_blocks    = (N_NODES + 255) / 256;
    const int w_blocks    = (256 * 64 + 255) / 256;
    const int px_blocks   = (N_NODES * 64 + 255) / 256;

    k_prepw<<<w_blocks, 256>>>(wl1, wr1, (uint32_t*)w1hi, (uint32_t*)w1lo);
    k_prepx<<<px_blocks, 256>>>(x);

    cudaEventRecord(ev_fork, 0);
    cudaStreamWaitEvent(s1, ev_fork, 0);
    k_prepw<<<w_blocks, 256, 0, s1>>>(wl2, wr2, (uint32_t*)w2hi, (uint32_t*)w2lo);

    k_gemm_tc<<<gemm_blocks, 256, SMEM_TOT>>>((const uint32_t*)w1hi, (const uint32_t*)w1lo);

    k_zero_deg<<<n_blocks, 256, 0, s1>>>();
    k_hist<<<e_blocks, 256, 0, s1>>>(dst);
    k_scan<<<1, 1024, 0, s1>>>();
    k_scatter<<<e_blocks, 256, 0, s1>>>(src, dst);
    cudaEventRecord(ev_join, s1);
    cudaStreamWaitEvent(0, ev_join, 0);

    k_node<1><<<node_blocks, 256>>>(att1, b1, (float*)h1_ptr);
    k_gemm_tc<<<gemm_blocks, 256, SMEM_TOT>>>((const uint32_t*)w2hi, (const uint32_t*)w2lo);
    k_node<2><<<node_blocks, 256>>>(att2, b2, out);
}

// round 10
// speedup vs baseline: 1.1090x; 1.1090x over previous
#include <cuda_runtime.h>
#include <cuda_bf16.h>
#include <math_constants.h>
#include <cstdint>

#define N_NODES 50000
#define HID     128
#define E_EDGES 640000
#define ATT_SLOPE 0.2f
#define OUT_SLOPE 0.01f

// ---------------- scratch (device globals; no allocation allowed) ----------
__device__ float g_xl[N_NODES * HID];    // layer-1 x_l (gemm1 out)
__device__ float g_xr[N_NODES * HID];    // layer-1 x_r (gemm1 out)
__device__ float g_xl2[N_NODES * HID];   // layer-2 x_l (gemm2 out)
__device__ float g_xr2[N_NODES * HID];   // layer-2 x_r (gemm2 out)
__device__ float g_h1[N_NODES * HID];
__device__ int   g_deg[N_NODES];
__device__ int   g_rowptr[N_NODES + 1];
__device__ int   g_cursor[N_NODES];
__device__ int   g_esrc[E_EDGES];
// bf16 hi/lo images: X rows [row][64 u32], W [n=256][64 u32]
__device__ uint32_t g_xhi[N_NODES * 64];
__device__ uint32_t g_xlo[N_NODES * 64];
__device__ uint32_t g_w1hi[256 * 64];
__device__ uint32_t g_w1lo[256 * 64];
__device__ uint32_t g_w2hi[256 * 64];
__device__ uint32_t g_w2lo[256 * 64];

__device__ __forceinline__ float lrelu(float x, float s) { return x > 0.f ? x : s * x; }

__device__ __forceinline__ uint32_t s2u(const void* p) {
    uint32_t a;
    asm("{ .reg .u64 t; cvta.to.shared.u64 t, %1; cvt.u32.u64 %0, t; }" : "=r"(a) : "l"(p));
    return a;
}
__device__ __forceinline__ void cpasync16(uint32_t dst, const void* src) {
    asm volatile("cp.async.cg.shared.global [%0], [%1], 16;" :: "r"(dst), "l"(src));
}
__device__ __forceinline__ void cpasync16p(uint32_t dst, const void* src, int sz) {
    asm volatile("cp.async.cg.shared.global [%0], [%1], 16, %2;"
                 :: "r"(dst), "l"(src), "r"(sz));
}

// ---------------- CSR build (unchanged) -------------------------------------
__global__ void k_zero_deg() {
    int i = blockIdx.x * blockDim.x + threadIdx.x;
    if (i < N_NODES) g_deg[i] = 0;
}
__global__ void k_hist(const int* __restrict__ dst) {
    int i = blockIdx.x * blockDim.x + threadIdx.x;
    if (i < E_EDGES) atomicAdd(&g_deg[dst[i]], 1);
}
__global__ void __launch_bounds__(1024) k_scan() {
    __shared__ int ssum[1024];
    const int t = threadIdx.x;
    const int CH = (N_NODES + 1023) / 1024;
    const int base = t * CH;
    int s = 0;
    for (int j = 0; j < CH; j++) { int idx = base + j; if (idx < N_NODES) s += g_deg[idx]; }
    ssum[t] = s;
    __syncthreads();
    for (int off = 1; off < 1024; off <<= 1) {
        int v = (t >= off) ? ssum[t - off] : 0;
        __syncthreads();
        ssum[t] += v;
        __syncthreads();
    }
    int run = (t == 0) ? 0 : ssum[t - 1];
    for (int j = 0; j < CH; j++) {
        int idx = base + j;
        if (idx < N_NODES) { g_rowptr[idx] = run; g_cursor[idx] = run; run += g_deg[idx]; }
    }
    if (t == 1023) g_rowptr[N_NODES] = ssum[1023];
}
__global__ void k_scatter(const int* __restrict__ src, const int* __restrict__ dst) {
    int i = blockIdx.x * blockDim.x + threadIdx.x;
    if (i < E_EDGES) {
        int p = atomicAdd(&g_cursor[dst[i]], 1);
        g_esrc[p] = src[i];
    }
}

// ---------------- bf16 split helpers ----------------------------------------
__device__ __forceinline__ uint32_t pack_hi(float x, float y) {
    __nv_bfloat16 hx = __float2bfloat16(x), hy = __float2bfloat16(y);
    return ((uint32_t)__bfloat16_as_ushort(hy) << 16) | __bfloat16_as_ushort(hx);
}
__device__ __forceinline__ uint32_t pack_lo(float x, float y) {
    __nv_bfloat16 hx = __float2bfloat16(x), hy = __float2bfloat16(y);
    __nv_bfloat16 lx = __float2bfloat16(x - __bfloat162float(hx));
    __nv_bfloat16 ly = __float2bfloat16(y - __bfloat162float(hy));
    return ((uint32_t)__bfloat16_as_ushort(ly) << 16) | __bfloat16_as_ushort(lx);
}

__global__ void k_prepw(const float* __restrict__ wl, const float* __restrict__ wr,
                        uint32_t* __restrict__ hi, uint32_t* __restrict__ lo) {
    int i = blockIdx.x * blockDim.x + threadIdx.x;
    if (i >= 256 * 64) return;
    int n = i >> 6, p = i & 63;
    const float* wp = ((n < 128) ? wl : wr) + (size_t)(n & 127) * 128 + p * 2;
    float2 v = *(const float2*)wp;
    hi[i] = pack_hi(v.x, v.y);
    lo[i] = pack_lo(v.x, v.y);
}

__global__ void k_prepx(const float* __restrict__ X) {
    int i = blockIdx.x * blockDim.x + threadIdx.x;
    if (i >= N_NODES * 64) return;
    float2 v = *(const float2*)(X + (size_t)i * 2);
    g_xhi[i] = pack_hi(v.x, v.y);
    g_xlo[i] = pack_lo(v.x, v.y);
}

// ---------------- split-bf16 HMMA GEMM (R7, + mbase + output ptrs) ----------
#define LDP   136
#define LDPU  68
#define SMEM_AHI 0
#define SMEM_ALO (SMEM_AHI + 128 * LDP * 2)
#define SMEM_BHI (SMEM_ALO + 128 * LDP * 2)
#define SMEM_BLO (SMEM_BHI + 64 * LDP * 2)
#define SMEM_TOT (SMEM_BLO + 64 * LDP * 2)

__device__ __forceinline__ void ldsm4(uint32_t& r0, uint32_t& r1, uint32_t& r2,
                                      uint32_t& r3, uint32_t addr) {
    asm volatile("ldmatrix.sync.aligned.m8n8.x4.shared.b16 {%0,%1,%2,%3}, [%4];"
                 : "=r"(r0), "=r"(r1), "=r"(r2), "=r"(r3) : "r"(addr));
}
__device__ __forceinline__ void mma16816(float* c, const uint32_t* a, const uint32_t* b) {
    asm volatile(
        "mma.sync.aligned.m16n8k16.row.col.f32.bf16.bf16.f32 "
        "{%0,%1,%2,%3}, {%4,%5,%6,%7}, {%8,%9}, {%0,%1,%2,%3};"
        : "+f"(c[0]), "+f"(c[1]), "+f"(c[2]), "+f"(c[3])
        : "r"(a[0]), "r"(a[1]), "r"(a[2]), "r"(a[3]), "r"(b[0]), "r"(b[1]));
}

__global__ void __launch_bounds__(256, 2)
k_gemm_tc(const uint32_t* __restrict__ whi, const uint32_t* __restrict__ wlo,
          float* __restrict__ out_l, float* __restrict__ out_r, int mbase) {
    extern __shared__ char smem[];
    const uint32_t sb = s2u(smem);
    const int tid  = threadIdx.x;
    const int warp = tid >> 5;
    const int lane = tid & 31;
    const int mblk = mbase + (blockIdx.x >> 2);
    const int nblk = blockIdx.x & 3;

    for (int c = tid; c < 2048; c += 256) {
        int row = c >> 4, seg = c & 15;
        long grow = (long)mblk * 128 + row;
        int sz = (grow < N_NODES) ? 16 : 0;
        uint32_t doff = (uint32_t)(row * (LDP * 2) + seg * 16);
        size_t soff = (size_t)grow * 256 + seg * 16;
        cpasync16p(sb + SMEM_AHI + doff, (const char*)g_xhi + soff, sz);
        cpasync16p(sb + SMEM_ALO + doff, (const char*)g_xlo + soff, sz);
    }
    {
        const char* bh = (const char*)(whi + (size_t)nblk * 64 * 64);
        const char* bl = (const char*)(wlo + (size_t)nblk * 64 * 64);
        for (int c = tid; c < 1024; c += 256) {
            int row = c >> 4, seg = c & 15;
            uint32_t doff = (uint32_t)(row * (LDP * 2) + seg * 16);
            uint32_t soff = (uint32_t)(row * 256 + seg * 16);
            cpasync16(sb + SMEM_BHI + doff, bh + soff);
            cpasync16(sb + SMEM_BLO + doff, bl + soff);
        }
    }
    asm volatile("cp.async.commit_group;" ::: "memory");
    asm volatile("cp.async.wait_group 0;" ::: "memory");
    __syncthreads();

    const int wm = (warp >> 1) * 32;
    const int wn = (warp & 1) * 32;
    float c[2][4][4];
#pragma unroll
    for (int mi = 0; mi < 2; mi++)
#pragma unroll
        for (int ni = 0; ni < 4; ni++)
#pragma unroll
            for (int q = 0; q < 4; q++) c[mi][ni][q] = 0.f;

    const uint32_t aRowOff = (uint32_t)((wm + (lane & 15)) * LDP + ((lane >> 4) << 3)) << 1;
    const uint32_t bRowOff = (uint32_t)((wn + ((lane >> 4) << 3) + (lane & 7)) * LDP
                                        + (((lane >> 3) & 1) << 3)) << 1;

#pragma unroll
    for (int term = 0; term < 3; term++) {
        const uint32_t Ab = sb + (term == 2 ? SMEM_ALO : SMEM_AHI) + aRowOff;
        const uint32_t Bb = sb + (term == 1 ? SMEM_BLO : SMEM_BHI) + bRowOff;
#pragma unroll
        for (int k0 = 0; k0 < 128; k0 += 16) {
            uint32_t a[2][4];
            ldsm4(a[0][0], a[0][1], a[0][2], a[0][3], Ab + (k0 << 1));
            ldsm4(a[1][0], a[1][1], a[1][2], a[1][3], Ab + ((16 * LDP) << 1) + (k0 << 1));
            uint32_t b[4][2];
#pragma unroll
            for (int nq = 0; nq < 2; nq++) {
                uint32_t r0, r1, r2, r3;
                ldsm4(r0, r1, r2, r3, Bb + ((nq * 16 * LDP) << 1) + (k0 << 1));
                b[nq * 2][0] = r0; b[nq * 2][1] = r1;
                b[nq * 2 + 1][0] = r2; b[nq * 2 + 1][1] = r3;
            }
#pragma unroll
            for (int mi = 0; mi < 2; mi++)
#pragma unroll
                for (int ni = 0; ni < 4; ni++)
                    mma16816(c[mi][ni], a[mi], b[ni]);
        }
    }

    float* buf = (nblk < 2) ? out_l : out_r;
    const int colbase = ((nblk * 64) & 127) + wn + (lane & 3) * 2;
#pragma unroll
    for (int mi = 0; mi < 2; mi++) {
#pragma unroll
        for (int half = 0; half < 2; half++) {
            long row = (long)mblk * 128 + wm + mi * 16 + (lane >> 2) + half * 8;
            if (row >= N_NODES) continue;
            float* rp = buf + row * HID + colbase;
#pragma unroll
            for (int ni = 0; ni < 4; ni++) {
                float2 v = make_float2(c[mi][ni][half * 2], c[mi][ni][half * 2 + 1]);
                *(float2*)(rp + ni * 8) = v;
            }
        }
    }
}

// ---------------- fused per-node attention (R7 body, + range + src bufs) ---
template <int LAYER>
__global__ void k_node(const float* __restrict__ att, const float* __restrict__ b,
                       const float* __restrict__ xlbuf, const float* __restrict__ xrbuf,
                       float* __restrict__ outbuf, int nbase, int nend) {
    const int n    = nbase + ((blockIdx.x * blockDim.x + threadIdx.x) >> 5);
    const int lane = threadIdx.x & 31;
    if (n >= nend) return;

    const int beg = g_rowptr[n];
    const int end = g_rowptr[n + 1];

    const float4 xr = *(const float4*)(xrbuf + (size_t)n * HID + lane * 4);
    const float4 at = *(const float4*)(att + lane * 4);

    float4 acc = make_float4(0.f, 0.f, 0.f, 0.f);
    float  sum = 0.f;

    for (int i0 = beg; i0 < end; i0 += 32) {
        const int cnt = min(32, end - i0);
        int sid = (lane < cnt) ? g_esrc[i0 + lane] : 0;
        for (int j = 0; j < cnt; j++) {
            const int s = __shfl_sync(0xffffffffu, sid, j);
            const float4 xl = *(const float4*)(xlbuf + (size_t)s * HID + lane * 4);
            float p = lrelu(xl.x + xr.x, ATT_SLOPE) * at.x
                    + lrelu(xl.y + xr.y, ATT_SLOPE) * at.y
                    + lrelu(xl.z + xr.z, ATT_SLOPE) * at.z
                    + lrelu(xl.w + xr.w, ATT_SLOPE) * at.w;
            p += __shfl_xor_sync(0xffffffffu, p, 8);
            p += __shfl_xor_sync(0xffffffffu, p, 4);
            p += __shfl_xor_sync(0xffffffffu, p, 2);
            p += __shfl_xor_sync(0xffffffffu, p, 1);
            const float ex = __expf(p);
            sum += ex;
            acc.x = fmaf(ex, xl.x, acc.x);
            acc.y = fmaf(ex, xl.y, acc.y);
            acc.z = fmaf(ex, xl.z, acc.z);
            acc.w = fmaf(ex, xl.w, acc.w);
        }
    }

    const float inv = 1.f / (sum + 1e-16f);
    const float4 bb = *(const float4*)(b + lane * 4);
    float4 o;
    o.x = fmaf(acc.x, inv, bb.x);
    o.y = fmaf(acc.y, inv, bb.y);
    o.z = fmaf(acc.z, inv, bb.z);
    o.w = fmaf(acc.w, inv, bb.w);

    float* dstp = outbuf + (size_t)n * HID + lane * 4;
    if (LAYER == 1) {
        o.x = lrelu(o.x, OUT_SLOPE);
        o.y = lrelu(o.y, OUT_SLOPE);
        o.z = lrelu(o.z, OUT_SLOPE);
        o.w = lrelu(o.w, OUT_SLOPE);
        *(float4*)dstp = o;
        // bf16 hi/lo image of h1 for the layer-2 GEMM
        const size_t ib = (size_t)n * 64 + lane * 2;
        uint2 hi = make_uint2(pack_hi(o.x, o.y), pack_hi(o.z, o.w));
        uint2 lo = make_uint2(pack_lo(o.x, o.y), pack_lo(o.z, o.w));
        *(uint2*)(g_xhi + ib) = hi;
        *(uint2*)(g_xlo + ib) = lo;
    } else {
        const float4 h = *(const float4*)(g_h1 + (size_t)n * HID + lane * 4);
        o.x += h.x; o.y += h.y; o.z += h.z; o.w += h.w;
        *(float4*)dstp = o;
    }
}

// ---------------- launch ----------------
extern "C" void kernel_launch(void* const* d_in, const int* in_sizes, int n_in,
                              void* d_out, int out_size) {
    const float* x    = (const float*)d_in[0];
    const int*   ei   = (const int*)d_in[1];
    const float* wl1  = (const float*)d_in[2];
    const float* wr1  = (const float*)d_in[3];
    const float* att1 = (const float*)d_in[4];
    const float* b1   = (const float*)d_in[5];
    const float* wl2  = (const float*)d_in[6];
    const float* wr2  = (const float*)d_in[7];
    const float* att2 = (const float*)d_in[8];
    const float* b2   = (const float*)d_in[9];
    float* out = (float*)d_out;

    const int* src = ei;
    const int* dst = ei + E_EDGES;

    void *h1_ptr, *xl_p, *xr_p, *xl2_p, *xr2_p;
    cudaGetSymbolAddress(&h1_ptr, g_h1);
    cudaGetSymbolAddress(&xl_p, g_xl);
    cudaGetSymbolAddress(&xr_p, g_xr);
    cudaGetSymbolAddress(&xl2_p, g_xl2);
    cudaGetSymbolAddress(&xr2_p, g_xr2);
    void *w1hi, *w1lo, *w2hi, *w2lo;
    cudaGetSymbolAddress(&w1hi, g_w1hi);
    cudaGetSymbolAddress(&w1lo, g_w1lo);
    cudaGetSymbolAddress(&w2hi, g_w2hi);
    cudaGetSymbolAddress(&w2lo, g_w2lo);

    static cudaStream_t s1 = nullptr;
    static cudaEvent_t ev_fork = nullptr, ev_csr = nullptr, ev_g2 = nullptr;
    static cudaEvent_t ev_chunk[4] = {nullptr, nullptr, nullptr, nullptr};
    if (s1 == nullptr) {
        cudaStreamCreateWithFlags(&s1, cudaStreamNonBlocking);
        cudaEventCreateWithFlags(&ev_fork, cudaEventDisableTiming);
        cudaEventCreateWithFlags(&ev_csr, cudaEventDisableTiming);
        cudaEventCreateWithFlags(&ev_g2, cudaEventDisableTiming);
        for (int q = 0; q < 4; q++)
            cudaEventCreateWithFlags(&ev_chunk[q], cudaEventDisableTiming);
    }

    cudaFuncSetAttribute(k_gemm_tc, cudaFuncAttributeMaxDynamicSharedMemorySize, SMEM_TOT);

    const int MBLKS = (N_NODES + 127) / 128;                // 391
    const int e_blocks = (E_EDGES + 255) / 256;
    const int n_blocks = (N_NODES + 255) / 256;
    const int w_blocks = (256 * 64 + 255) / 256;
    const int px_blocks = (N_NODES * 64 + 255) / 256;

    // node1 chunks: offsets divisible by 128 so gemm2 mblk ranges are clean
    const int coff[5] = {0, 12544, 25088, 37632, N_NODES};

    // ---- s0: prep + gemm1.  s1: prepw2 + CSR build (overlapped) ----
    k_prepw<<<w_blocks, 256>>>(wl1, wr1, (uint32_t*)w1hi, (uint32_t*)w1lo);
    k_prepx<<<px_blocks, 256>>>(x);

    cudaEventRecord(ev_fork, 0);
    cudaStreamWaitEvent(s1, ev_fork, 0);
    k_prepw<<<w_blocks, 256, 0, s1>>>(wl2, wr2, (uint32_t*)w2hi, (uint32_t*)w2lo);

    k_gemm_tc<<<MBLKS * 4, 256, SMEM_TOT>>>((const uint32_t*)w1hi, (const uint32_t*)w1lo,
                                            (float*)xl_p, (float*)xr_p, 0);

    k_zero_deg<<<n_blocks, 256, 0, s1>>>();
    k_hist<<<e_blocks, 256, 0, s1>>>(dst);
    k_scan<<<1, 1024, 0, s1>>>();
    k_scatter<<<e_blocks, 256, 0, s1>>>(src, dst);
    cudaEventRecord(ev_csr, s1);
    cudaStreamWaitEvent(0, ev_csr, 0);

    // ---- node1 in 4 chunks on s0; gemm2 chunk q on s1 (separate out bufs) --
    for (int q = 0; q < 4; q++) {
        const int nodes = coff[q + 1] - coff[q];
        const int blocks = (nodes * 32 + 255) / 256;
        k_node<1><<<blocks, 256>>>(att1, b1, (const float*)xl_p, (const float*)xr_p,
                                   (float*)h1_ptr, coff[q], coff[q + 1]);
        cudaEventRecord(ev_chunk[q], 0);
        cudaStreamWaitEvent(s1, ev_chunk[q], 0);
        const int m0 = coff[q] / 128;
        const int m1 = (q == 3) ? MBLKS : coff[q + 1] / 128;
        k_gemm_tc<<<(m1 - m0) * 4, 256, SMEM_TOT, s1>>>((const uint32_t*)w2hi,
                                                        (const uint32_t*)w2lo,
                                                        (float*)xl2_p, (float*)xr2_p, m0);
    }
    cudaEventRecord(ev_g2, s1);
    cudaStreamWaitEvent(0, ev_g2, 0);

    // ---- node2 (full) reads gemm2 buffers ----
    k_node<2><<<(N_NODES * 32 + 255) / 256, 256>>>(att2, b2,
                                                   (const float*)xl2_p, (const float*)xr2_p,
                                                   out, 0, N_NODES);
}